// round 2
// baseline (speedup 1.0000x reference)
#include <cuda_runtime.h>
#include <cuda_bf16.h>
#include <cstdint>

#define B 32
#define H 32
#define D 128
#define R 512
#define S 4096
#define HID 4096
#define SCALE 0.08838834764831845f

// ---------------- scratch (static device, no allocation) ----------------
__device__ float g_q[B * HID];            // q projection result
__device__ float g_part[4 * B * HID];     // split-K partials (reused 3x)
__device__ float g_qa[B * H * R];         // absorbed query
__device__ float g_scores[B * H * S];     // scores -> attn probs (in place)
__device__ float g_ctx[B * H * R];        // latent context
__device__ float g_attn[B * HID];         // after value absorption

// ---------------- helpers ----------------
__device__ __forceinline__ void split4(float4 v, __nv_bfloat16* hi, __nv_bfloat16* lo) {
    float a[4] = {v.x, v.y, v.z, v.w};
#pragma unroll
    for (int i = 0; i < 4; i++) {
        __nv_bfloat16 h = __float2bfloat16(a[i]);
        hi[i] = h;
        lo[i] = __float2bfloat16(a[i] - __bfloat162float(h));
    }
}

__device__ __forceinline__ void mma16816(float* c, const uint32_t* a, uint32_t b0, uint32_t b1) {
    asm volatile(
        "mma.sync.aligned.m16n8k16.row.col.f32.bf16.bf16.f32 "
        "{%0,%1,%2,%3},{%4,%5,%6,%7},{%8,%9},{%0,%1,%2,%3};\n"
        : "+f"(c[0]), "+f"(c[1]), "+f"(c[2]), "+f"(c[3])
        : "r"(a[0]), "r"(a[1]), "r"(a[2]), "r"(a[3]), "r"(b0), "r"(b1));
}

// ---------------- fp32 GEMM-NT with split-K:  C[32,4096] = A[32,4096] @ W[4096,4096]^T
// grid (64 ntiles of 64, 4 ksplits), block 256. Writes partials to g_part.
__global__ void gemm_nt32_k(const float* __restrict__ A, const float* __restrict__ W) {
    const int nb = blockIdx.x * 64;
    const int ks = blockIdx.y;
    const int kbeg = ks * 1024;
    __shared__ float As[32][33];
    __shared__ float Bs[64][33];
    const int tid = threadIdx.x;
    const int ty = tid / 16, tx = tid % 16;   // m = ty*2, n = tx*4
    float acc[2][4] = {};
    for (int k0 = kbeg; k0 < kbeg + 1024; k0 += 32) {
        {
            int r = tid / 8, c = (tid % 8) * 4;
            float4 v = *reinterpret_cast<const float4*>(A + r * HID + k0 + c);
            As[r][c] = v.x; As[r][c + 1] = v.y; As[r][c + 2] = v.z; As[r][c + 3] = v.w;
        }
#pragma unroll
        for (int it = 0; it < 2; it++) {
            int i = tid + it * 256;
            int r = i / 8, c = (i % 8) * 4;
            float4 v = *reinterpret_cast<const float4*>(W + (nb + r) * HID + k0 + c);
            Bs[r][c] = v.x; Bs[r][c + 1] = v.y; Bs[r][c + 2] = v.z; Bs[r][c + 3] = v.w;
        }
        __syncthreads();
#pragma unroll
        for (int k = 0; k < 32; k++) {
            float a0 = As[ty * 2][k], a1 = As[ty * 2 + 1][k];
            float b0 = Bs[tx * 4][k], b1 = Bs[tx * 4 + 1][k];
            float b2 = Bs[tx * 4 + 2][k], b3 = Bs[tx * 4 + 3][k];
            acc[0][0] += a0 * b0; acc[0][1] += a0 * b1; acc[0][2] += a0 * b2; acc[0][3] += a0 * b3;
            acc[1][0] += a1 * b0; acc[1][1] += a1 * b1; acc[1][2] += a1 * b2; acc[1][3] += a1 * b3;
        }
        __syncthreads();
    }
#pragma unroll
    for (int i = 0; i < 2; i++)
#pragma unroll
        for (int j = 0; j < 4; j++)
            g_part[ks * (B * HID) + (ty * 2 + i) * HID + nb + tx * 4 + j] = acc[i][j];
}

// ---------------- reduce 4 partials (+ optional bias); grid 512, block 256
__global__ void reduce4_k(float* __restrict__ dst, const float* __restrict__ bias) {
    int i = blockIdx.x * 256 + threadIdx.x;   // < 131072
    float v = g_part[i] + g_part[131072 + i] + g_part[2 * 131072 + i] + g_part[3 * 131072 + i];
    if (bias) v += bias[i & (HID - 1)];
    dst[i] = v;
}

// ---------------- q_absorbed[b,h,r] = sum_d q[b,h*128+d] * w_kc[h,d,r]
// grid (4 rtiles of 128, 32 h), block 256
__global__ void qabsorb_k(const float* __restrict__ w_kc) {
    const int h = blockIdx.y;
    const int r0 = blockIdx.x * 128;
    __shared__ float As[32][33];    // [b][d]
    __shared__ float Bs[32][132];   // [d][r]
    const int tid = threadIdx.x;
    const int ty = tid / 32, tx = tid % 32;   // b = ty*4+i, r = tx*4+j
    float acc[4][4] = {};
    for (int d0 = 0; d0 < 128; d0 += 32) {
        {
            int r = tid / 8, c = (tid % 8) * 4;
            float4 v = *reinterpret_cast<const float4*>(g_q + r * HID + h * D + d0 + c);
            As[r][c] = v.x; As[r][c + 1] = v.y; As[r][c + 2] = v.z; As[r][c + 3] = v.w;
        }
#pragma unroll
        for (int it = 0; it < 4; it++) {
            int i = tid + it * 256;
            int rr = i / 32, c = (i % 32) * 4;
            float4 v = *reinterpret_cast<const float4*>(w_kc + (h * D + d0 + rr) * R + r0 + c);
            *reinterpret_cast<float4*>(&Bs[rr][c]) = v;
        }
        __syncthreads();
#pragma unroll
        for (int dd = 0; dd < 32; dd++) {
            float4 bv = *reinterpret_cast<float4*>(&Bs[dd][tx * 4]);
            float bb[4] = {bv.x, bv.y, bv.z, bv.w};
#pragma unroll
            for (int i = 0; i < 4; i++) {
                float a = As[ty * 4 + i][dd];
#pragma unroll
                for (int j = 0; j < 4; j++) acc[i][j] += a * bb[j];
            }
        }
        __syncthreads();
    }
#pragma unroll
    for (int i = 0; i < 4; i++)
#pragma unroll
        for (int j = 0; j < 4; j++)
            g_qa[((ty * 4 + i) * H + h) * R + r0 + tx * 4 + j] = acc[i][j];
}

// ---------------- scores[b,h,s] = SCALE * sum_r qa[b,h,r]*ckv[b,s,r]
// bf16 hi/lo split MMA. grid (32 stiles of 128, 32 b), block 256 (8 warps: 2m x 4n)
__global__ void scores_k(const float* __restrict__ ckv) {
    const int b = blockIdx.y;
    const int s0 = blockIdx.x * 128;
    __shared__ __nv_bfloat16 Ah[32][72], Al[32][72];     // [h][r]
    __shared__ __nv_bfloat16 Bh[128][72], Bl[128][72];   // [s][r]
    const int tid = threadIdx.x;
    const int warp = tid >> 5, lane = tid & 31;
    const int g = lane >> 2, t = lane & 3;
    const int mw = warp >> 2, nw = warp & 3;
    float c[4][4] = {};
    const float* Aptr = g_qa + (b * H) * R;
    const float* Bptr = ckv + (size_t)(b * S + s0) * R;
    for (int k0 = 0; k0 < R; k0 += 64) {
#pragma unroll
        for (int it = 0; it < 2; it++) {
            int i = tid + it * 256;
            int r = i >> 4, cc = (i & 15) * 4;
            float4 v = *reinterpret_cast<const float4*>(Aptr + r * R + k0 + cc);
            split4(v, &Ah[r][cc], &Al[r][cc]);
        }
#pragma unroll
        for (int it = 0; it < 8; it++) {
            int i = tid + it * 256;
            int r = i >> 4, cc = (i & 15) * 4;
            float4 v = *reinterpret_cast<const float4*>(Bptr + r * R + k0 + cc);
            split4(v, &Bh[r][cc], &Bl[r][cc]);
        }
        __syncthreads();
#pragma unroll
        for (int kk = 0; kk < 4; kk++) {
            int kc = kk * 16 + 2 * t;
            int m0 = mw * 16 + g;
            uint32_t ah[4], al[4];
            ah[0] = *reinterpret_cast<uint32_t*>(&Ah[m0][kc]);
            ah[1] = *reinterpret_cast<uint32_t*>(&Ah[m0 + 8][kc]);
            ah[2] = *reinterpret_cast<uint32_t*>(&Ah[m0][kc + 8]);
            ah[3] = *reinterpret_cast<uint32_t*>(&Ah[m0 + 8][kc + 8]);
            al[0] = *reinterpret_cast<uint32_t*>(&Al[m0][kc]);
            al[1] = *reinterpret_cast<uint32_t*>(&Al[m0 + 8][kc]);
            al[2] = *reinterpret_cast<uint32_t*>(&Al[m0][kc + 8]);
            al[3] = *reinterpret_cast<uint32_t*>(&Al[m0 + 8][kc + 8]);
#pragma unroll
            for (int j = 0; j < 4; j++) {
                int n = nw * 32 + j * 8 + g;
                uint32_t bh0 = *reinterpret_cast<uint32_t*>(&Bh[n][kc]);
                uint32_t bh1 = *reinterpret_cast<uint32_t*>(&Bh[n][kc + 8]);
                uint32_t bl0 = *reinterpret_cast<uint32_t*>(&Bl[n][kc]);
                uint32_t bl1 = *reinterpret_cast<uint32_t*>(&Bl[n][kc + 8]);
                mma16816(c[j], ah, bh0, bh1);
                mma16816(c[j], ah, bl0, bl1);
                mma16816(c[j], al, bh0, bh1);
            }
        }
        __syncthreads();
    }
#pragma unroll
    for (int j = 0; j < 4; j++) {
        int n = s0 + nw * 32 + j * 8 + 2 * t;
        int m = mw * 16 + g;
        float* o = g_scores + (size_t)(b * H + m) * S + n;
        o[0] = c[j][0] * SCALE; o[1] = c[j][1] * SCALE;
        o += 8 * (size_t)S;
        o[0] = c[j][2] * SCALE; o[1] = c[j][3] * SCALE;
    }
}

// ---------------- row softmax over S=4096; grid 1024 rows, block 256
__global__ void softmax_k() {
    float* row = g_scores + (size_t)blockIdx.x * S;
    const int tid = threadIdx.x;
    float v[16];
    float mx = -1e30f;
#pragma unroll
    for (int i = 0; i < 16; i++) { v[i] = row[tid + i * 256]; mx = fmaxf(mx, v[i]); }
#pragma unroll
    for (int o = 16; o; o >>= 1) mx = fmaxf(mx, __shfl_xor_sync(0xffffffffu, mx, o));
    __shared__ float sm[8];
    if ((tid & 31) == 0) sm[tid >> 5] = mx;
    __syncthreads();
    float m = sm[0];
#pragma unroll
    for (int w = 1; w < 8; w++) m = fmaxf(m, sm[w]);
    __syncthreads();
    float sum = 0.f;
#pragma unroll
    for (int i = 0; i < 16; i++) { v[i] = __expf(v[i] - m); sum += v[i]; }
#pragma unroll
    for (int o = 16; o; o >>= 1) sum += __shfl_xor_sync(0xffffffffu, sum, o);
    if ((tid & 31) == 0) sm[tid >> 5] = sum;
    __syncthreads();
    float tot = 0.f;
#pragma unroll
    for (int w = 0; w < 8; w++) tot += sm[w];
    float inv = 1.f / tot;
#pragma unroll
    for (int i = 0; i < 16; i++) row[tid + i * 256] = v[i] * inv;
}

// ---------------- ctx[b,h,r] = sum_s P[b,h,s]*ckv[b,s,r]
// bf16 hi/lo MMA. B kept [k=s][n=r] in smem (natural layout), fragments packed from u16.
// grid (4 rtiles of 128, 32 b), block 256
__global__ void ctx_k(const float* __restrict__ ckv) {
    const int b = blockIdx.y;
    const int r0 = blockIdx.x * 128;
    __shared__ __nv_bfloat16 Ah[32][72], Al[32][72];     // [h][s-chunk]
    __shared__ __nv_bfloat16 Bh[64][136], Bl[64][136];   // [s-chunk][r]
    const int tid = threadIdx.x;
    const int warp = tid >> 5, lane = tid & 31;
    const int g = lane >> 2, t = lane & 3;
    const int mw = warp >> 2, nw = warp & 3;
    float c[4][4] = {};
    const float* Aptr = g_scores + (size_t)(b * H) * S;
    for (int k0 = 0; k0 < S; k0 += 64) {
#pragma unroll
        for (int it = 0; it < 2; it++) {
            int i = tid + it * 256;
            int r = i >> 4, cc = (i & 15) * 4;
            float4 v = *reinterpret_cast<const float4*>(Aptr + (size_t)r * S + k0 + cc);
            split4(v, &Ah[r][cc], &Al[r][cc]);
        }
#pragma unroll
        for (int it = 0; it < 8; it++) {
            int i = tid + it * 256;
            int srow = i >> 5, rc = (i & 31) * 4;
            float4 v = *reinterpret_cast<const float4*>(ckv + (size_t)(b * S + k0 + srow) * R + r0 + rc);
            split4(v, &Bh[srow][rc], &Bl[srow][rc]);
        }
        __syncthreads();
#pragma unroll
        for (int kk = 0; kk < 4; kk++) {
            int kc = kk * 16 + 2 * t;
            int m0 = mw * 16 + g;
            uint32_t ah[4], al[4];
            ah[0] = *reinterpret_cast<uint32_t*>(&Ah[m0][kc]);
            ah[1] = *reinterpret_cast<uint32_t*>(&Ah[m0 + 8][kc]);
            ah[2] = *reinterpret_cast<uint32_t*>(&Ah[m0][kc + 8]);
            ah[3] = *reinterpret_cast<uint32_t*>(&Ah[m0 + 8][kc + 8]);
            al[0] = *reinterpret_cast<uint32_t*>(&Al[m0][kc]);
            al[1] = *reinterpret_cast<uint32_t*>(&Al[m0 + 8][kc]);
            al[2] = *reinterpret_cast<uint32_t*>(&Al[m0][kc + 8]);
            al[3] = *reinterpret_cast<uint32_t*>(&Al[m0 + 8][kc + 8]);
#pragma unroll
            for (int j = 0; j < 4; j++) {
                int n = nw * 32 + j * 8 + g;
                uint32_t h00 = *reinterpret_cast<unsigned short*>(&Bh[kc][n]);
                uint32_t h01 = *reinterpret_cast<unsigned short*>(&Bh[kc + 1][n]);
                uint32_t h10 = *reinterpret_cast<unsigned short*>(&Bh[kc + 8][n]);
                uint32_t h11 = *reinterpret_cast<unsigned short*>(&Bh[kc + 9][n]);
                uint32_t l00 = *reinterpret_cast<unsigned short*>(&Bl[kc][n]);
                uint32_t l01 = *reinterpret_cast<unsigned short*>(&Bl[kc + 1][n]);
                uint32_t l10 = *reinterpret_cast<unsigned short*>(&Bl[kc + 8][n]);
                uint32_t l11 = *reinterpret_cast<unsigned short*>(&Bl[kc + 9][n]);
                uint32_t bh0 = h00 | (h01 << 16);
                uint32_t bh1 = h10 | (h11 << 16);
                uint32_t bl0 = l00 | (l01 << 16);
                uint32_t bl1 = l10 | (l11 << 16);
                mma16816(c[j], ah, bh0, bh1);
                mma16816(c[j], ah, bl0, bl1);
                mma16816(c[j], al, bh0, bh1);
            }
        }
        __syncthreads();
    }
#pragma unroll
    for (int j = 0; j < 4; j++) {
        int n = r0 + nw * 32 + j * 8 + 2 * t;
        int m = mw * 16 + g;
        float* o = g_ctx + (size_t)(b * H + m) * R + n;
        o[0] = c[j][0]; o[1] = c[j][1];
        o += 8 * (size_t)R;
        o[0] = c[j][2]; o[1] = c[j][3];
    }
}

// ---------------- attn_out[b,h*128+d] partial = sum_{r in ks range} ctx[b,h,r]*w_vc[h,r,d]
// grid (4 ksplits of 128, 32 h), block 256. Writes g_part.
__global__ void vabsorb_k(const float* __restrict__ w_vc) {
    const int h = blockIdx.y;
    const int ks = blockIdx.x;
    __shared__ float As[32][33];    // [b][r-chunk]
    __shared__ float Bs[32][132];   // [r-chunk][d]
    const int tid = threadIdx.x;
    const int ty = tid / 32, tx = tid % 32;   // b = ty*4+i, d = tx*4+j
    float acc[4][4] = {};
    for (int r0 = ks * 128; r0 < ks * 128 + 128; r0 += 32) {
        {
            int r = tid / 8, c = (tid % 8) * 4;
            float4 v = *reinterpret_cast<const float4*>(g_ctx + (r * H + h) * R + r0 + c);
            As[r][c] = v.x; As[r][c + 1] = v.y; As[r][c + 2] = v.z; As[r][c + 3] = v.w;
        }
#pragma unroll
        for (int it = 0; it < 4; it++) {
            int i = tid + it * 256;
            int rr = i / 32, c = (i % 32) * 4;
            float4 v = *reinterpret_cast<const float4*>(w_vc + (h * R + r0 + rr) * D + c);
            *reinterpret_cast<float4*>(&Bs[rr][c]) = v;
        }
        __syncthreads();
#pragma unroll
        for (int dd = 0; dd < 32; dd++) {
            float4 bv = *reinterpret_cast<float4*>(&Bs[dd][tx * 4]);
            float bb[4] = {bv.x, bv.y, bv.z, bv.w};
#pragma unroll
            for (int i = 0; i < 4; i++) {
                float a = As[ty * 4 + i][dd];
#pragma unroll
                for (int j = 0; j < 4; j++) acc[i][j] += a * bb[j];
            }
        }
        __syncthreads();
    }
#pragma unroll
    for (int i = 0; i < 4; i++)
#pragma unroll
        for (int j = 0; j < 4; j++)
            g_part[(ks * B + ty * 4 + i) * HID + h * D + tx * 4 + j] = acc[i][j];
}

// ---------------- launch ----------------
extern "C" void kernel_launch(void* const* d_in, const int* in_sizes, int n_in,
                              void* d_out, int out_size) {
    const float* hs   = (const float*)d_in[0];
    const float* ckv  = (const float*)d_in[1];
    const float* q_w  = (const float*)d_in[2];
    const float* q_b  = (const float*)d_in[3];
    const float* w_kc = (const float*)d_in[4];
    const float* w_vc = (const float*)d_in[5];
    const float* o_w  = (const float*)d_in[6];
    const float* o_b  = (const float*)d_in[7];
    float* out = (float*)d_out;

    float *pq, *pattn;
    cudaGetSymbolAddress((void**)&pq, g_q);
    cudaGetSymbolAddress((void**)&pattn, g_attn);

    gemm_nt32_k<<<dim3(64, 4), 256>>>(hs, q_w);
    reduce4_k<<<512, 256>>>(pq, q_b);
    qabsorb_k<<<dim3(4, 32), 256>>>(w_kc);
    scores_k<<<dim3(32, 32), 256>>>(ckv);
    softmax_k<<<1024, 256>>>();
    ctx_k<<<dim3(4, 32), 256>>>(ckv);
    vabsorb_k<<<dim3(4, 32), 256>>>(w_vc);
    reduce4_k<<<512, 256>>>(pattn, nullptr);
    gemm_nt32_k<<<dim3(64, 4), 256>>>(pattn, o_w);
    reduce4_k<<<512, 256>>>(out, o_b);
}

// round 3
// speedup vs baseline: 1.4197x; 1.4197x over previous
#include <cuda_runtime.h>
#include <cuda_bf16.h>
#include <cstdint>

#define B 32
#define H 32
#define D 128
#define R 512
#define S 4096
#define HID 4096
#define SCALE 0.08838834764831845f
#define NSPLIT 8
#define SB (S / NSPLIT)
#define SC 32
#define NCHUNK (SB / SC)

// ---------------- scratch ----------------
__device__ float g_q[B * HID];
__device__ float g_part[4 * B * HID];
__device__ float g_qa[B * H * R];
__device__ float g_ctx[B * H * R];
__device__ float g_attn[B * HID];
__device__ float g_ctxp[NSPLIT * B * H * R];
__device__ float g_m[NSPLIT * B * H];
__device__ float g_l[NSPLIT * B * H];

// ---------------- helpers ----------------
__device__ __forceinline__ uint32_t pack2(__nv_bfloat16 a, __nv_bfloat16 b) {
    return (uint32_t)__bfloat16_as_ushort(a) | ((uint32_t)__bfloat16_as_ushort(b) << 16);
}
__device__ __forceinline__ void split_store(float4 v, __nv_bfloat16* hp, __nv_bfloat16* lp) {
    __nv_bfloat16 h0 = __float2bfloat16(v.x), h1 = __float2bfloat16(v.y),
                  h2 = __float2bfloat16(v.z), h3 = __float2bfloat16(v.w);
    __nv_bfloat16 l0 = __float2bfloat16(v.x - __bfloat162float(h0));
    __nv_bfloat16 l1 = __float2bfloat16(v.y - __bfloat162float(h1));
    __nv_bfloat16 l2 = __float2bfloat16(v.z - __bfloat162float(h2));
    __nv_bfloat16 l3 = __float2bfloat16(v.w - __bfloat162float(h3));
    *reinterpret_cast<uint2*>(hp) = make_uint2(pack2(h0, h1), pack2(h2, h3));
    *reinterpret_cast<uint2*>(lp) = make_uint2(pack2(l0, l1), pack2(l2, l3));
}
__device__ __forceinline__ uint32_t saddr(const void* p) {
    return (uint32_t)__cvta_generic_to_shared(p);
}
__device__ __forceinline__ void ldsm4(uint32_t* r, const void* p) {
    asm volatile("ldmatrix.sync.aligned.m8n8.x4.shared.b16 {%0,%1,%2,%3},[%4];\n"
                 : "=r"(r[0]), "=r"(r[1]), "=r"(r[2]), "=r"(r[3]) : "r"(saddr(p)));
}
__device__ __forceinline__ void ldsm4t(uint32_t* r, const void* p) {
    asm volatile("ldmatrix.sync.aligned.m8n8.x4.trans.shared.b16 {%0,%1,%2,%3},[%4];\n"
                 : "=r"(r[0]), "=r"(r[1]), "=r"(r[2]), "=r"(r[3]) : "r"(saddr(p)));
}
__device__ __forceinline__ void mma16816(float* c, const uint32_t* a, uint32_t b0, uint32_t b1) {
    asm volatile(
        "mma.sync.aligned.m16n8k16.row.col.f32.bf16.bf16.f32 "
        "{%0,%1,%2,%3},{%4,%5,%6,%7},{%8,%9},{%0,%1,%2,%3};\n"
        : "+f"(c[0]), "+f"(c[1]), "+f"(c[2]), "+f"(c[3])
        : "r"(a[0]), "r"(a[1]), "r"(a[2]), "r"(a[3]), "r"(b0), "r"(b1));
}

// ---------------- bf16 hi/lo GEMM-NT: C[32,4096] = A[32,4096] @ W[4096,4096]^T
// grid (32 ntiles of 128, 4 ksplits), block 256. Partials -> g_part.
__global__ void __launch_bounds__(256) gemm_bf_k(const float* __restrict__ A,
                                                 const float* __restrict__ W) {
    const int n0 = blockIdx.x * 128;
    const int ks = blockIdx.y;
    __shared__ __nv_bfloat16 Ah[32][40], Al[32][40];
    __shared__ __nv_bfloat16 Wh[128][40], Wl[128][40];
    const int tid = threadIdx.x;
    const int warp = tid >> 5, lane = tid & 31;
    const int g = lane >> 2, t = lane & 3;
    float c[2][2][4] = {};
    for (int k0 = ks * 1024; k0 < ks * 1024 + 1024; k0 += 32) {
        {
            int r = tid >> 3, cc = (tid & 7) * 4;
            float4 v = *reinterpret_cast<const float4*>(A + r * HID + k0 + cc);
            split_store(v, &Ah[r][cc], &Al[r][cc]);
        }
#pragma unroll
        for (int it = 0; it < 4; it++) {
            int i = it * 256 + tid;
            int r = i >> 3, cc = (i & 7) * 4;
            float4 v = *reinterpret_cast<const float4*>(W + (size_t)(n0 + r) * HID + k0 + cc);
            split_store(v, &Wh[r][cc], &Wl[r][cc]);
        }
        __syncthreads();
#pragma unroll
        for (int kk = 0; kk < 2; kk++) {
            uint32_t ah[2][4], al[2][4];
#pragma unroll
            for (int mi = 0; mi < 2; mi++) {
                ldsm4(ah[mi], &Ah[mi * 16 + (lane & 15)][kk * 16 + (lane >> 4) * 8]);
                ldsm4(al[mi], &Al[mi * 16 + (lane & 15)][kk * 16 + (lane >> 4) * 8]);
            }
            int brow = warp * 16 + ((lane >> 4) << 3) + (lane & 7);
            int bcol = kk * 16 + (((lane >> 3) & 1) << 3);
            uint32_t bh[4], bl[4];
            ldsm4(bh, &Wh[brow][bcol]);
            ldsm4(bl, &Wl[brow][bcol]);
#pragma unroll
            for (int nf = 0; nf < 2; nf++)
#pragma unroll
                for (int mi = 0; mi < 2; mi++) {
                    mma16816(c[mi][nf], ah[mi], bh[nf * 2], bh[nf * 2 + 1]);
                    mma16816(c[mi][nf], ah[mi], bl[nf * 2], bl[nf * 2 + 1]);
                    mma16816(c[mi][nf], al[mi], bh[nf * 2], bh[nf * 2 + 1]);
                }
        }
        __syncthreads();
    }
#pragma unroll
    for (int mi = 0; mi < 2; mi++)
#pragma unroll
        for (int nf = 0; nf < 2; nf++) {
            int row = mi * 16 + g;
            int col = n0 + warp * 16 + nf * 8 + 2 * t;
            float* o = g_part + ks * (B * HID) + (size_t)row * HID + col;
            *reinterpret_cast<float2*>(o) = make_float2(c[mi][nf][0], c[mi][nf][1]);
            *reinterpret_cast<float2*>(o + 8 * HID) = make_float2(c[mi][nf][2], c[mi][nf][3]);
        }
}

// ---------------- reduce 4 partials (+ optional bias); grid 512, block 256
__global__ void reduce4_k(float* __restrict__ dst, const float* __restrict__ bias) {
    int i = blockIdx.x * 256 + threadIdx.x;
    float v = g_part[i] + g_part[131072 + i] + g_part[2 * 131072 + i] + g_part[3 * 131072 + i];
    if (bias) v += bias[i & (HID - 1)];
    dst[i] = v;
}

// ---------------- q_absorbed[b,h,r] = sum_d q[b,h*128+d] * w_kc[h,d,r]
__global__ void qabsorb_k(const float* __restrict__ w_kc) {
    const int h = blockIdx.y;
    const int r0 = blockIdx.x * 128;
    __shared__ float As[32][33];
    __shared__ float Bs[32][132];
    const int tid = threadIdx.x;
    const int ty = tid / 32, tx = tid % 32;
    float acc[4][4] = {};
    for (int d0 = 0; d0 < 128; d0 += 32) {
        {
            int r = tid / 8, c = (tid % 8) * 4;
            float4 v = *reinterpret_cast<const float4*>(g_q + r * HID + h * D + d0 + c);
            As[r][c] = v.x; As[r][c + 1] = v.y; As[r][c + 2] = v.z; As[r][c + 3] = v.w;
        }
#pragma unroll
        for (int it = 0; it < 4; it++) {
            int i = tid + it * 256;
            int rr = i / 32, c = (i % 32) * 4;
            float4 v = *reinterpret_cast<const float4*>(w_kc + (size_t)(h * D + d0 + rr) * R + r0 + c);
            *reinterpret_cast<float4*>(&Bs[rr][c]) = v;
        }
        __syncthreads();
#pragma unroll
        for (int dd = 0; dd < 32; dd++) {
            float4 bv = *reinterpret_cast<float4*>(&Bs[dd][tx * 4]);
            float bb[4] = {bv.x, bv.y, bv.z, bv.w};
#pragma unroll
            for (int i = 0; i < 4; i++) {
                float a = As[ty * 4 + i][dd];
#pragma unroll
                for (int j = 0; j < 4; j++) acc[i][j] += a * bb[j];
            }
        }
        __syncthreads();
    }
#pragma unroll
    for (int i = 0; i < 4; i++)
#pragma unroll
        for (int j = 0; j < 4; j++)
            g_qa[((ty * 4 + i) * H + h) * R + r0 + tx * 4 + j] = acc[i][j];
}

// ---------------- fused flash MLA: per (split, batch) CTA, block 256 ----------------
#define AST 520
#define PST 40
#define OFF_AH 0
#define OFF_AL 33280
#define OFF_VH 66560
#define OFF_VL 99840
#define OFF_PH 133120
#define OFF_PL 135680
#define OFF_SRED 138240
#define OFF_WMAX 142848
#define OFF_WSUM 143104
#define OFF_MROW 143360
#define OFF_LROW 143488
#define OFF_ALPHA 143616
#define SMEM_FMLA 143744

__global__ void __launch_bounds__(256, 1) fmla_k(const float* __restrict__ ckv) {
    extern __shared__ char smbuf[];
    __nv_bfloat16* Ah = reinterpret_cast<__nv_bfloat16*>(smbuf + OFF_AH);
    __nv_bfloat16* Al = reinterpret_cast<__nv_bfloat16*>(smbuf + OFF_AL);
    __nv_bfloat16* Vh = reinterpret_cast<__nv_bfloat16*>(smbuf + OFF_VH);
    __nv_bfloat16* Vl = reinterpret_cast<__nv_bfloat16*>(smbuf + OFF_VL);
    __nv_bfloat16* Ph = reinterpret_cast<__nv_bfloat16*>(smbuf + OFF_PH);
    __nv_bfloat16* Pl = reinterpret_cast<__nv_bfloat16*>(smbuf + OFF_PL);
    float* Sred = reinterpret_cast<float*>(smbuf + OFF_SRED);
    float* wmax = reinterpret_cast<float*>(smbuf + OFF_WMAX);
    float* wsum = reinterpret_cast<float*>(smbuf + OFF_WSUM);
    float* mrow = reinterpret_cast<float*>(smbuf + OFF_MROW);
    float* lrow = reinterpret_cast<float*>(smbuf + OFF_LROW);
    float* salpha = reinterpret_cast<float*>(smbuf + OFF_ALPHA);

    const int sp = blockIdx.x, b = blockIdx.y;
    const int tid = threadIdx.x;
    const int warp = tid >> 5, lane = tid & 31;
    const int g = lane >> 2, t = lane & 3;
    const int kw = warp >> 2, mw = (warp >> 1) & 1, nw = warp & 1;

#pragma unroll
    for (int it = 0; it < 16; it++) {
        int i = it * 256 + tid;
        int row = i >> 7, cc = (i & 127) * 4;
        float4 v = *reinterpret_cast<const float4*>(g_qa + (size_t)(b * H + row) * R + cc);
        split_store(v, &Ah[row * AST + cc], &Al[row * AST + cc]);
    }
    if (tid < 32) { mrow[tid] = -3e38f; lrow[tid] = 0.f; }

    float cv[2][8][4] = {};

    for (int ch = 0; ch < NCHUNK; ch++) {
        __syncthreads();
        size_t sbase = (size_t)b * S + sp * SB + ch * SC;
#pragma unroll
        for (int it = 0; it < 16; it++) {
            int i = it * 256 + tid;
            int s = i >> 7, rc = (i & 127) * 4;
            float4 v = *reinterpret_cast<const float4*>(ckv + (sbase + s) * R + rc);
            split_store(v, &Vh[s * AST + rc], &Vl[s * AST + rc]);
        }
        __syncthreads();

        // ---- QK: 32(h) x 32(s); warp = (kw,mw,nw); k split over r ----
        float cq[2][4] = {};
#pragma unroll
        for (int kk = 0; kk < 16; kk++) {
            int k0 = kw * 256 + kk * 16;
            uint32_t ah[4], al[4];
            ldsm4(ah, &Ah[(mw * 16 + (lane & 15)) * AST + k0 + (lane >> 4) * 8]);
            ldsm4(al, &Al[(mw * 16 + (lane & 15)) * AST + k0 + (lane >> 4) * 8]);
            int brow = nw * 16 + ((lane >> 4) << 3) + (lane & 7);
            int bcol = k0 + (((lane >> 3) & 1) << 3);
            uint32_t bh[4], bl[4];
            ldsm4(bh, &Vh[brow * AST + bcol]);
            ldsm4(bl, &Vl[brow * AST + bcol]);
#pragma unroll
            for (int nf = 0; nf < 2; nf++) {
                mma16816(cq[nf], ah, bh[nf * 2], bh[nf * 2 + 1]);
                mma16816(cq[nf], ah, bl[nf * 2], bl[nf * 2 + 1]);
                mma16816(cq[nf], al, bh[nf * 2], bh[nf * 2 + 1]);
            }
        }
        if (kw == 1) {
#pragma unroll
            for (int nf = 0; nf < 2; nf++) {
                int col = nw * 16 + nf * 8 + 2 * t;
                int rA = mw * 16 + g;
                *reinterpret_cast<float2*>(&Sred[rA * 36 + col]) = make_float2(cq[nf][0], cq[nf][1]);
                *reinterpret_cast<float2*>(&Sred[(rA + 8) * 36 + col]) = make_float2(cq[nf][2], cq[nf][3]);
            }
        }
        __syncthreads();
        if (kw == 0) {
            float mA = -3e38f, mB = -3e38f;
#pragma unroll
            for (int nf = 0; nf < 2; nf++) {
                int col = nw * 16 + nf * 8 + 2 * t;
                int rA = mw * 16 + g;
                float2 r0 = *reinterpret_cast<float2*>(&Sred[rA * 36 + col]);
                float2 r1 = *reinterpret_cast<float2*>(&Sred[(rA + 8) * 36 + col]);
                cq[nf][0] = (cq[nf][0] + r0.x) * SCALE;
                cq[nf][1] = (cq[nf][1] + r0.y) * SCALE;
                cq[nf][2] = (cq[nf][2] + r1.x) * SCALE;
                cq[nf][3] = (cq[nf][3] + r1.y) * SCALE;
                mA = fmaxf(mA, fmaxf(cq[nf][0], cq[nf][1]));
                mB = fmaxf(mB, fmaxf(cq[nf][2], cq[nf][3]));
            }
            mA = fmaxf(mA, __shfl_xor_sync(0xffffffffu, mA, 1));
            mA = fmaxf(mA, __shfl_xor_sync(0xffffffffu, mA, 2));
            mB = fmaxf(mB, __shfl_xor_sync(0xffffffffu, mB, 1));
            mB = fmaxf(mB, __shfl_xor_sync(0xffffffffu, mB, 2));
            if (t == 0) {
                wmax[nw * 32 + mw * 16 + g] = mA;
                wmax[nw * 32 + mw * 16 + g + 8] = mB;
            }
        }
        __syncthreads();
        if (warp == 0) {
            float cm = fmaxf(wmax[lane], wmax[32 + lane]);
            float mo = mrow[lane];
            float mn = fmaxf(mo, cm);
            salpha[lane] = __expf(mo - mn);
            mrow[lane] = mn;
        }
        __syncthreads();
        {
            float a0 = salpha[g], a1 = salpha[g + 8], a2 = salpha[g + 16], a3 = salpha[g + 24];
#pragma unroll
            for (int mi = 0; mi < 2; mi++) {
                float rA = mi ? a2 : a0, rB = mi ? a3 : a1;
#pragma unroll
                for (int nj = 0; nj < 8; nj++) {
                    cv[mi][nj][0] *= rA; cv[mi][nj][1] *= rA;
                    cv[mi][nj][2] *= rB; cv[mi][nj][3] *= rB;
                }
            }
        }
        if (kw == 0) {
            int rA = mw * 16 + g;
            float mA = mrow[rA], mB = mrow[rA + 8];
            float sA = 0.f, sB = 0.f;
#pragma unroll
            for (int nf = 0; nf < 2; nf++) {
                float p0 = __expf(cq[nf][0] - mA), p1 = __expf(cq[nf][1] - mA);
                float p2 = __expf(cq[nf][2] - mB), p3 = __expf(cq[nf][3] - mB);
                sA += p0 + p1; sB += p2 + p3;
                int col = nw * 16 + nf * 8 + 2 * t;
                __nv_bfloat16 h0 = __float2bfloat16(p0), h1 = __float2bfloat16(p1);
                __nv_bfloat16 h2 = __float2bfloat16(p2), h3 = __float2bfloat16(p3);
                *reinterpret_cast<uint32_t*>(&Ph[rA * PST + col]) = pack2(h0, h1);
                *reinterpret_cast<uint32_t*>(&Ph[(rA + 8) * PST + col]) = pack2(h2, h3);
                __nv_bfloat16 l0 = __float2bfloat16(p0 - __bfloat162float(h0));
                __nv_bfloat16 l1 = __float2bfloat16(p1 - __bfloat162float(h1));
                __nv_bfloat16 l2 = __float2bfloat16(p2 - __bfloat162float(h2));
                __nv_bfloat16 l3 = __float2bfloat16(p3 - __bfloat162float(h3));
                *reinterpret_cast<uint32_t*>(&Pl[rA * PST + col]) = pack2(l0, l1);
                *reinterpret_cast<uint32_t*>(&Pl[(rA + 8) * PST + col]) = pack2(l2, l3);
            }
            sA += __shfl_xor_sync(0xffffffffu, sA, 1);
            sA += __shfl_xor_sync(0xffffffffu, sA, 2);
            sB += __shfl_xor_sync(0xffffffffu, sB, 1);
            sB += __shfl_xor_sync(0xffffffffu, sB, 2);
            if (t == 0) { wsum[nw * 32 + rA] = sA; wsum[nw * 32 + rA + 8] = sB; }
        }
        __syncthreads();
        if (warp == 0) lrow[lane] = lrow[lane] * salpha[lane] + wsum[lane] + wsum[32 + lane];

        // ---- PV: ctx(32 x warp-n64) += P(32x32) @ V(32x512) ----
#pragma unroll
        for (int kk = 0; kk < 2; kk++) {
            int k0 = kk * 16;
            uint32_t ph[2][4], pl[2][4];
#pragma unroll
            for (int mi = 0; mi < 2; mi++) {
                ldsm4(ph[mi], &Ph[(mi * 16 + (lane & 15)) * PST + k0 + (lane >> 4) * 8]);
                ldsm4(pl[mi], &Pl[(mi * 16 + (lane & 15)) * PST + k0 + (lane >> 4) * 8]);
            }
#pragma unroll
            for (int j = 0; j < 4; j++) {
                int nbase = warp * 64 + j * 16;
                int vrow = k0 + (lane & 7) + (((lane >> 3) & 1) << 3);
                int vcol = nbase + (lane >> 4) * 8;
                uint32_t vh[4], vl[4];
                ldsm4t(vh, &Vh[vrow * AST + vcol]);
                ldsm4t(vl, &Vl[vrow * AST + vcol]);
#pragma unroll
                for (int half = 0; half < 2; half++)
#pragma unroll
                    for (int mi = 0; mi < 2; mi++) {
                        float* cc = cv[mi][j * 2 + half];
                        mma16816(cc, ph[mi], vh[half * 2], vh[half * 2 + 1]);
                        mma16816(cc, ph[mi], vl[half * 2], vl[half * 2 + 1]);
                        mma16816(cc, pl[mi], vh[half * 2], vh[half * 2 + 1]);
                    }
            }
        }
    }
    __syncthreads();
    if (warp == 0) {
        g_m[(sp * B + b) * H + lane] = mrow[lane];
        g_l[(sp * B + b) * H + lane] = lrow[lane];
    }
#pragma unroll
    for (int mi = 0; mi < 2; mi++)
#pragma unroll
        for (int nj = 0; nj < 8; nj++) {
            int row = mi * 16 + g;
            int col = warp * 64 + nj * 8 + 2 * t;
            float* o = g_ctxp + ((size_t)(sp * B + b) * H + row) * R + col;
            *reinterpret_cast<float2*>(o) = make_float2(cv[mi][nj][0], cv[mi][nj][1]);
            *reinterpret_cast<float2*>(o + 8 * R) = make_float2(cv[mi][nj][2], cv[mi][nj][3]);
        }
}

// ---------------- combine split partials -> g_ctx; grid B*H, block 128 ----------------
__global__ void combine_k() {
    int bh = blockIdx.x;
    __shared__ float w[NSPLIT];
    __shared__ float invL;
    if (threadIdx.x == 0) {
        float M = -3e38f;
#pragma unroll
        for (int sp = 0; sp < NSPLIT; sp++) M = fmaxf(M, g_m[sp * (B * H) + bh]);
        float L = 0.f;
#pragma unroll
        for (int sp = 0; sp < NSPLIT; sp++) {
            float ww = __expf(g_m[sp * (B * H) + bh] - M);
            w[sp] = ww;
            L += ww * g_l[sp * (B * H) + bh];
        }
        invL = 1.f / L;
    }
    __syncthreads();
    for (int r = threadIdx.x; r < R; r += blockDim.x) {
        float acc = 0.f;
#pragma unroll
        for (int sp = 0; sp < NSPLIT; sp++)
            acc += w[sp] * g_ctxp[((size_t)sp * (B * H) + bh) * R + r];
        g_ctx[(size_t)bh * R + r] = acc * invL;
    }
}

// ---------------- attn partial = sum_r ctx[b,h,r]*w_vc[h,r,d]; grid (4 ks, 32 h) ----------------
__global__ void vabsorb_k(const float* __restrict__ w_vc) {
    const int h = blockIdx.y;
    const int ks = blockIdx.x;
    __shared__ float As[32][33];
    __shared__ float Bs[32][132];
    const int tid = threadIdx.x;
    const int ty = tid / 32, tx = tid % 32;
    float acc[4][4] = {};
    for (int r0 = ks * 128; r0 < ks * 128 + 128; r0 += 32) {
        {
            int r = tid / 8, c = (tid % 8) * 4;
            float4 v = *reinterpret_cast<const float4*>(g_ctx + (size_t)(r * H + h) * R + r0 + c);
            As[r][c] = v.x; As[r][c + 1] = v.y; As[r][c + 2] = v.z; As[r][c + 3] = v.w;
        }
#pragma unroll
        for (int it = 0; it < 4; it++) {
            int i = tid + it * 256;
            int rr = i / 32, c = (i % 32) * 4;
            float4 v = *reinterpret_cast<const float4*>(w_vc + (size_t)(h * R + r0 + rr) * D + c);
            *reinterpret_cast<float4*>(&Bs[rr][c]) = v;
        }
        __syncthreads();
#pragma unroll
        for (int dd = 0; dd < 32; dd++) {
            float4 bv = *reinterpret_cast<float4*>(&Bs[dd][tx * 4]);
            float bb[4] = {bv.x, bv.y, bv.z, bv.w};
#pragma unroll
            for (int i = 0; i < 4; i++) {
                float a = As[ty * 4 + i][dd];
#pragma unroll
                for (int j = 0; j < 4; j++) acc[i][j] += a * bb[j];
            }
        }
        __syncthreads();
    }
#pragma unroll
    for (int i = 0; i < 4; i++)
#pragma unroll
        for (int j = 0; j < 4; j++)
            g_part[(ks * B + ty * 4 + i) * HID + h * D + tx * 4 + j] = acc[i][j];
}

// ---------------- launch ----------------
extern "C" void kernel_launch(void* const* d_in, const int* in_sizes, int n_in,
                              void* d_out, int out_size) {
    const float* hs   = (const float*)d_in[0];
    const float* ckv  = (const float*)d_in[1];
    const float* q_w  = (const float*)d_in[2];
    const float* q_b  = (const float*)d_in[3];
    const float* w_kc = (const float*)d_in[4];
    const float* w_vc = (const float*)d_in[5];
    const float* o_w  = (const float*)d_in[6];
    const float* o_b  = (const float*)d_in[7];
    float* out = (float*)d_out;

    float *pq, *pattn;
    cudaGetSymbolAddress((void**)&pq, g_q);
    cudaGetSymbolAddress((void**)&pattn, g_attn);
    cudaFuncSetAttribute(fmla_k, cudaFuncAttributeMaxDynamicSharedMemorySize, SMEM_FMLA);

    gemm_bf_k<<<dim3(32, 4), 256>>>(hs, q_w);
    reduce4_k<<<512, 256>>>(pq, q_b);
    qabsorb_k<<<dim3(4, 32), 256>>>(w_kc);
    fmla_k<<<dim3(NSPLIT, B), 256, SMEM_FMLA>>>(ckv);
    combine_k<<<B * H, 128>>>();
    vabsorb_k<<<dim3(4, 32), 256>>>(w_vc);
    reduce4_k<<<512, 256>>>(pattn, nullptr);
    gemm_bf_k<<<dim3(32, 4), 256>>>(pattn, o_w);
    reduce4_k<<<512, 256>>>(out, o_b);
}